// round 13
// baseline (speedup 1.0000x reference)
#include <cuda_runtime.h>
#include <cuda_bf16.h>
#include <math.h>

#define B_  8
#define C_  128
#define N_  4096
#define C2_ 64

// ---------------- scratch ----------------
__device__ __align__(16) __nv_bfloat16 g_qs[B_*N_*128];    // [b][n][k] k:0-63 hi, 64-127 lo
__device__ __align__(16) float g_v [B_*C2_*N_];
__device__ __align__(16) float g_xc[B_*C2_*N_];
__device__ __align__(16) float g_rspart[B_*32*32*128];     // rowsum partials (b,nt,mt,row)
__device__ __align__(16) __nv_bfloat16 g_invsbf[B_*2*N_];  // [b][hi/lo][n]
__device__ __align__(16) __nv_bfloat16 g_av[B_*128*N_];    // [b][r][n] r:0-63 hi(v*invs), 64-127 lo
__device__ __align__(16) float g_t [B_*C2_*N_];
__device__ __align__(16) float g_part[2*64*256];
__device__ __align__(16) float g_bn[128];
__device__ __align__(16) __nv_bfloat16 g_ph[(size_t)B_*N_*N_];  // hi plane of exp(E), UPPER tiles only
__device__ __align__(16) __nv_bfloat16 g_pl[(size_t)B_*N_*N_];  // lo plane, UPPER tiles only

// ---------------- helpers ----------------
__device__ __forceinline__ unsigned smem_u32(const void* p){
    unsigned a; asm("{ .reg .u64 t; cvta.to.shared.u64 t, %1; cvt.u32.u64 %0, t; }" : "=r"(a) : "l"(p)); return a;
}
__device__ __forceinline__ void ldsm_x4(unsigned* r, unsigned addr){
    asm volatile("ldmatrix.sync.aligned.m8n8.x4.shared.b16 {%0,%1,%2,%3}, [%4];"
        : "=r"(r[0]), "=r"(r[1]), "=r"(r[2]), "=r"(r[3]) : "r"(addr));
}
__device__ __forceinline__ void ldsm_x2(unsigned* r, unsigned addr){
    asm volatile("ldmatrix.sync.aligned.m8n8.x2.shared.b16 {%0,%1}, [%2];"
        : "=r"(r[0]), "=r"(r[1]) : "r"(addr));
}
__device__ __forceinline__ void ldsm_x4_t(unsigned* r, unsigned addr){
    asm volatile("ldmatrix.sync.aligned.m8n8.x4.trans.shared.b16 {%0,%1,%2,%3}, [%4];"
        : "=r"(r[0]), "=r"(r[1]), "=r"(r[2]), "=r"(r[3]) : "r"(addr));
}
__device__ __forceinline__ void ldsm_x2_t(unsigned* r, unsigned addr){
    asm volatile("ldmatrix.sync.aligned.m8n8.x2.trans.shared.b16 {%0,%1}, [%2];"
        : "=r"(r[0]), "=r"(r[1]) : "r"(addr));
}
__device__ __forceinline__ void mma16816(float* c, const unsigned* a, const unsigned* b){
    asm volatile("mma.sync.aligned.m16n8k16.row.col.f32.bf16.bf16.f32 "
        "{%0,%1,%2,%3}, {%4,%5,%6,%7}, {%8,%9}, {%0,%1,%2,%3};"
        : "+f"(c[0]), "+f"(c[1]), "+f"(c[2]), "+f"(c[3])
        : "r"(a[0]), "r"(a[1]), "r"(a[2]), "r"(a[3]), "r"(b[0]), "r"(b[1]));
}
__device__ __forceinline__ void cp16(unsigned s, const void* g){
    asm volatile("{ .reg .u64 gp; cvta.to.global.u64 gp, %1; cp.async.cg.shared.global [%0], [gp], 16; }"
        :: "r"(s), "l"(g));
}
#define CP_COMMIT() asm volatile("cp.async.commit_group;" ::: "memory")
#define CP_WAIT(n)  asm volatile("cp.async.wait_group %0;" :: "n"(n) : "memory")

__device__ __forceinline__ unsigned packbf(__nv_bfloat16 a, __nv_bfloat16 b){
    return (unsigned)__bfloat16_as_ushort(a) | ((unsigned)__bfloat16_as_ushort(b) << 16);
}
__device__ __forceinline__ unsigned sw128(int row, unsigned off){ return off ^ (unsigned)((row & 7) << 4); }

// ================= K1: projections via split-bf16 HMMA =================
#define P_WH 0
#define P_WL 52224
#define P_XH 104448
#define P_XL 139264
#define P_SMEM 174080
__global__ void __launch_bounds__(256)
k_proj(const float* __restrict__ x, const float* __restrict__ w_qk,
       const float* __restrict__ w_v, const float* __restrict__ b_v,
       const float* __restrict__ w_x)
{
    extern __shared__ char smc[];
    unsigned sb = smem_u32(smc);
    int b = blockIdx.y, nt = blockIdx.x;
    int tid = threadIdx.x, wid = tid >> 5, lane = tid & 31;

    unsigned short* WH = (unsigned short*)(smc + P_WH);
    unsigned short* WL = (unsigned short*)(smc + P_WL);
    for (int i = tid; i < 24576; i += 256) {
        float wv = (i < 8192) ? w_qk[i] : (i < 16384 ? w_v[i - 8192] : w_x[i - 16384]);
        int row = i >> 7, cc = i & 127;
        __nv_bfloat16 h = __float2bfloat16(wv);
        __nv_bfloat16 l = __float2bfloat16(wv - __bfloat162float(h));
        WH[row * 136 + cc] = __bfloat16_as_ushort(h);
        WL[row * 136 + cc] = __bfloat16_as_ushort(l);
    }
    unsigned short* XH = (unsigned short*)(smc + P_XH);
    unsigned short* XL = (unsigned short*)(smc + P_XL);
    const float* xp = x + (size_t)(b * C_) * N_ + nt * 128;
    for (int i = tid; i < 16384; i += 256) {
        int c = i >> 7, n = i & 127;
        float v = xp[(size_t)c * N_ + n];
        __nv_bfloat16 h = __float2bfloat16(v);
        __nv_bfloat16 l = __float2bfloat16(v - __bfloat162float(h));
        XH[c * 136 + n] = __bfloat16_as_ushort(h);
        XL[c * 136 + n] = __bfloat16_as_ushort(l);
    }
    __syncthreads();

    int wn = wid >> 1, wm = wid & 1;
    int rm = wn * 48, cn = wm * 64;
    float c[3][8][4];
#pragma unroll
    for (int ti = 0; ti < 3; ti++)
#pragma unroll
        for (int tj = 0; tj < 8; tj++)
#pragma unroll
            for (int q = 0; q < 4; q++) c[ti][tj][q] = 0.f;

#pragma unroll
    for (int p = 0; p < 3; p++) {
        unsigned wa = sb + ((p == 2) ? P_WL : P_WH);
        unsigned xb = sb + ((p == 1) ? P_XL : P_XH);
#pragma unroll
        for (int ks = 0; ks < 8; ks++) {
            unsigned a[3][4];
#pragma unroll
            for (int ti = 0; ti < 3; ti++)
                ldsm_x4(a[ti], wa + (rm + ti * 16 + (lane & 15)) * 272 + ks * 32 + (lane >> 4) * 16);
#pragma unroll
            for (int tjp = 0; tjp < 4; tjp++) {
                unsigned bb[4];
                ldsm_x4_t(bb, xb + (ks * 16 + (lane & 15)) * 272
                              + (cn + tjp * 16 + ((lane >> 4) << 3)) * 2);
#pragma unroll
                for (int ti = 0; ti < 3; ti++) {
                    mma16816(c[ti][2 * tjp],     a[ti], bb);
                    mma16816(c[ti][2 * tjp + 1], a[ti], bb + 2);
                }
            }
        }
    }
    __syncthreads();

    unsigned short* qstage = (unsigned short*)(smc + P_XH);
#pragma unroll
    for (int ti = 0; ti < 3; ti++) {
        int r0 = rm + ti * 16;
        int r = r0 + (lane >> 2);
#pragma unroll
        for (int tj = 0; tj < 8; tj++) {
            int c0 = cn + tj * 8 + 2 * (lane & 3);
            float v0 = c[ti][tj][0], v1 = c[ti][tj][1], v2 = c[ti][tj][2], v3 = c[ti][tj][3];
            if (r0 < 64) {
                __nv_bfloat16 h0 = __float2bfloat16(v0), h1 = __float2bfloat16(v1);
                __nv_bfloat16 h2 = __float2bfloat16(v2), h3 = __float2bfloat16(v3);
                qstage[c0 * 128 + r]            = __bfloat16_as_ushort(h0);
                qstage[c0 * 128 + 64 + r]       = __bfloat16_as_ushort(__float2bfloat16(v0 - __bfloat162float(h0)));
                qstage[(c0 + 1) * 128 + r]      = __bfloat16_as_ushort(h1);
                qstage[(c0 + 1) * 128 + 64 + r] = __bfloat16_as_ushort(__float2bfloat16(v1 - __bfloat162float(h1)));
                qstage[c0 * 128 + r + 8]            = __bfloat16_as_ushort(h2);
                qstage[c0 * 128 + 64 + r + 8]       = __bfloat16_as_ushort(__float2bfloat16(v2 - __bfloat162float(h2)));
                qstage[(c0 + 1) * 128 + r + 8]      = __bfloat16_as_ushort(h3);
                qstage[(c0 + 1) * 128 + 64 + r + 8] = __bfloat16_as_ushort(__float2bfloat16(v3 - __bfloat162float(h3)));
            } else if (r0 < 128) {
                float ba = b_v[r - 64], bb2 = b_v[r - 56];
                *(float2*)&g_v[(size_t)(b * 64 + r - 64) * N_ + nt * 128 + c0] = make_float2(v0 + ba, v1 + ba);
                *(float2*)&g_v[(size_t)(b * 64 + r - 56) * N_ + nt * 128 + c0] = make_float2(v2 + bb2, v3 + bb2);
            } else {
                *(float2*)&g_xc[(size_t)(b * 64 + r - 128) * N_ + nt * 128 + c0] = make_float2(v0, v1);
                *(float2*)&g_xc[(size_t)(b * 64 + r - 120) * N_ + nt * 128 + c0] = make_float2(v2, v3);
            }
        }
    }
    __syncthreads();
    for (int i = tid; i < 2048; i += 256) {
        int row = i >> 4, cc = i & 15;
        ((uint4*)(g_qs + (size_t)(b * N_ + nt * 128 + row) * 128))[cc] =
            ((const uint4*)(qstage + row * 128))[cc];
    }
}

// ================= K2: symmetric E=Q^T Q, P=exp(E) upper tiles only, rowsums both sides ===
#define K2_AS 0
#define K2_BS 34816
#define K2_RED 0
#define K2_RDT 4096
#define K2_SMEM 69632
__global__ void __launch_bounds__(256, 2)
k_energy()
{
    extern __shared__ char smc[];
    unsigned sb = smem_u32(smc);
    int b = blockIdx.y;
    int tid = threadIdx.x, wid = tid >> 5, lane = tid & 31;

    int u = blockIdx.x, nt = 0;
    while (u >= 32 - nt) { u -= 32 - nt; nt++; }
    int mt = nt + u;

    {
        const uint4* asrc = (const uint4*)(g_qs + (size_t)(b * N_ + nt * 128) * 128);
        const uint4* bsrc = (const uint4*)(g_qs + (size_t)(b * N_ + mt * 128) * 128);
        for (int i = tid; i < 2048; i += 256) {
            int row = i >> 4, cc = i & 15;
            *(uint4*)(smc + K2_AS + row * 272 + cc * 16) = asrc[i];
            *(uint4*)(smc + K2_BS + row * 272 + cc * 16) = bsrc[i];
        }
    }
    __syncthreads();

    int wn = wid >> 1, wm = wid & 1;
    int rn = wn * 32, cm = wm * 64;
    float c[2][8][4];
#pragma unroll
    for (int ti = 0; ti < 2; ti++)
#pragma unroll
        for (int tj = 0; tj < 8; tj++)
#pragma unroll
            for (int q = 0; q < 4; q++) c[ti][tj][q] = 0.f;

    const int qa[3] = {0, 0, 1}, qb[3] = {0, 1, 0};
#pragma unroll
    for (int s = 0; s < 12; s++) {
        int grp = s >> 2, km = (s & 3) * 32;
        int ka = qa[grp] * 128 + km, kb = qb[grp] * 128 + km;
        unsigned a[2][4];
#pragma unroll
        for (int ti = 0; ti < 2; ti++)
            ldsm_x4(a[ti], sb + K2_AS + (rn + ti * 16 + (lane & 15)) * 272 + ka + (lane >> 4) * 16);
#pragma unroll
        for (int tjp = 0; tjp < 4; tjp++) {
            unsigned bb[4];
            ldsm_x4(bb, sb + K2_BS + (cm + tjp * 16 + ((lane >> 4) << 3) + (lane & 7)) * 272
                        + kb + ((lane >> 3) & 1) * 16);
            mma16816(c[0][2*tjp],   a[0], bb);     mma16816(c[1][2*tjp],   a[1], bb);
            mma16816(c[0][2*tjp+1], a[0], bb + 2); mma16816(c[1][2*tjp+1], a[1], bb + 2);
        }
    }

    bool offd = (mt != nt);
    float rsA[2] = {0.f, 0.f}, rsB[2] = {0.f, 0.f};
    float colp0[8], colp1[8];
#pragma unroll
    for (int tj = 0; tj < 8; tj++) { colp0[tj] = 0.f; colp1[tj] = 0.f; }
    size_t prow = (size_t)(b * N_ + nt * 128) * N_ + mt * 128;
#pragma unroll
    for (int ti = 0; ti < 2; ti++) {
        int r0 = rn + ti * 16 + (lane >> 2);
#pragma unroll
        for (int tj = 0; tj < 8; tj++) {
            int c0 = cm + tj * 8 + 2 * (lane & 3);
            float p0 = __expf(c[ti][tj][0]), p1 = __expf(c[ti][tj][1]);
            float p2 = __expf(c[ti][tj][2]), p3 = __expf(c[ti][tj][3]);
            rsA[ti] += p0 + p1;  rsB[ti] += p2 + p3;
            colp0[tj] += p0 + p2; colp1[tj] += p1 + p3;
            __nv_bfloat16 h0 = __float2bfloat16(p0), h1 = __float2bfloat16(p1);
            __nv_bfloat16 h2 = __float2bfloat16(p2), h3 = __float2bfloat16(p3);
            __nv_bfloat16 l0 = __float2bfloat16(p0 - __bfloat162float(h0));
            __nv_bfloat16 l1 = __float2bfloat16(p1 - __bfloat162float(h1));
            __nv_bfloat16 l2 = __float2bfloat16(p2 - __bfloat162float(h2));
            __nv_bfloat16 l3 = __float2bfloat16(p3 - __bfloat162float(h3));
            size_t ba = prow + (size_t)r0 * N_ + c0;
            size_t bc = ba + (size_t)8 * N_;
            *(unsigned*)(g_ph + ba) = packbf(h0, h1);
            *(unsigned*)(g_pl + ba) = packbf(l0, l1);
            *(unsigned*)(g_ph + bc) = packbf(h2, h3);
            *(unsigned*)(g_pl + bc) = packbf(l2, l3);
        }
    }
    if (offd) {
#pragma unroll
        for (int tj = 0; tj < 8; tj++) {
            colp0[tj] += __shfl_xor_sync(0xffffffff, colp0[tj], 4);
            colp0[tj] += __shfl_xor_sync(0xffffffff, colp0[tj], 8);
            colp0[tj] += __shfl_xor_sync(0xffffffff, colp0[tj], 16);
            colp1[tj] += __shfl_xor_sync(0xffffffff, colp1[tj], 4);
            colp1[tj] += __shfl_xor_sync(0xffffffff, colp1[tj], 8);
            colp1[tj] += __shfl_xor_sync(0xffffffff, colp1[tj], 16);
        }
    }
    __syncthreads();

    float* red  = (float*)(smc + K2_RED);
    float* redT = (float*)(smc + K2_RDT);
#pragma unroll
    for (int ti = 0; ti < 2; ti++) {
        int r0 = rn + ti * 16 + (lane >> 2);
        red[r0 * 8 + wm * 4 + (lane & 3)]       = rsA[ti];
        red[(r0 + 8) * 8 + wm * 4 + (lane & 3)] = rsB[ti];
    }
    if (offd && lane < 4) {
#pragma unroll
        for (int tj = 0; tj < 8; tj++) {
            redT[wn * 128 + cm + tj * 8 + 2 * lane]     = colp0[tj];
            redT[wn * 128 + cm + tj * 8 + 2 * lane + 1] = colp1[tj];
        }
    }
    __syncthreads();
    if (tid < 128) {
        float s = 0.f;
#pragma unroll
        for (int j = 0; j < 8; j++) s += red[tid * 8 + j];
        g_rspart[((size_t)(b * 32 + nt) * 32 + mt) * 128 + tid] = s;
        if (offd) {
            float st = redT[tid] + redT[128 + tid] + redT[256 + tid] + redT[384 + tid];
            g_rspart[((size_t)(b * 32 + mt) * 32 + nt) * 128 + tid] = st;
        }
    }
}

// ================= K2.5: rowsum reduce -> invsbf, Av = v*inv split (merged) =================
__global__ void k_rowav()
{
    int idx = blockIdx.x * 256 + threadIdx.x;
    int b = idx >> 12, n = idx & 4095;
    float s = 0.f;
    const float* p = g_rspart + ((size_t)(b * 32 + (n >> 7)) * 32) * 128 + (n & 127);
#pragma unroll
    for (int mt = 0; mt < 32; mt++) s += p[mt * 128];
    float inv = 1.0f / s;
    __nv_bfloat16 ih = __float2bfloat16(inv);
    g_invsbf[(b * 2 + 0) * N_ + n] = ih;
    g_invsbf[(b * 2 + 1) * N_ + n] = __float2bfloat16(inv - __bfloat162float(ih));
    const float* vs = g_v + (size_t)(b * 64) * N_ + n;
    __nv_bfloat16* avh = g_av + (size_t)(b * 128) * N_ + n;
#pragma unroll 4
    for (int o = 0; o < 64; o++) {
        float a = vs[(size_t)o * N_] * inv;
        __nv_bfloat16 h = __float2bfloat16(a);
        avh[(size_t)o * N_]        = h;
        avh[(size_t)(o + 64) * N_] = __float2bfloat16(a - __bfloat162float(h));
    }
}

// ================= K3: D = Av@(Ph+Pl); 256 thr/CTA, 2 CTA/SM, 1 mt-tile/CTA, 2-stage ===
// grid (32, 8) = 256 blocks (single wave). Warp tile 32x64 (8 warps). Swizzled stages.
#define K3_CS    1024            // [128] f32
#define K3_RS    1536            // [64][4] f32
#define K3_RQ    2560            // [64][4] f32
#define K3_STG   4096
#define K3_SSZ   51200           // A 16384 | H 16384 | L 16384 | INV 2048
#define K3_AO    0
#define K3_HO    16384
#define K3_LO    32768
#define K3_IO    49152
#define K3_DS    4096            // epilogue Ds overlay [128][132] f32
#define K3_WTE   71680           // epilogue w_t [64][64] f32
#define K3_SMEM  (4096 + 2*51200)   // 106496
__device__ __forceinline__ void k3_issue(unsigned sb, int st, int b, int mta, int ch, int tid)
{
    unsigned s0 = sb + K3_STG + st * K3_SSZ;
    int nb = ch << 6;
    bool tr = (mta > (ch >> 1));
    const __nv_bfloat16* asrc = g_av + (size_t)b * 128 * N_ + nb;
    const __nv_bfloat16 *hsrc, *lsrc;
    if (!tr) {
        hsrc = g_ph + ((size_t)(b * N_ + mta * 128)) * N_ + nb;
        lsrc = g_pl + ((size_t)(b * N_ + mta * 128)) * N_ + nb;
    } else {
        hsrc = g_ph + ((size_t)(b * N_ + nb)) * N_ + mta * 128;
        lsrc = g_pl + ((size_t)(b * N_ + nb)) * N_ + mta * 128;
    }
    for (int i = tid; i < 1024; i += 256) {
        int ar = i >> 3, ac = i & 7;
        cp16(s0 + K3_AO + sw128(ar, ar * 128 + ac * 16), asrc + (size_t)ar * N_ + ac * 8);
        if (!tr) {
            unsigned doff = sw128(ar, ar * 128 + ac * 16);
            cp16(s0 + K3_HO + doff, hsrc + (size_t)ar * N_ + ac * 8);
            cp16(s0 + K3_LO + doff, lsrc + (size_t)ar * N_ + ac * 8);
        } else {
            int rr = i >> 4, cc = i & 15;
            unsigned doff = sw128(rr, rr * 256 + cc * 16);
            cp16(s0 + K3_HO + doff, hsrc + (size_t)rr * N_ + cc * 8);
            cp16(s0 + K3_LO + doff, lsrc + (size_t)rr * N_ + cc * 8);
        }
    }
    if (tid < 16) {
        int row = tid >> 3, cc = tid & 7;
        cp16(s0 + K3_IO + sw128(row, row * 128 + cc * 16),
             g_invsbf + (size_t)(b * 2 + row) * N_ + nb + cc * 8);
    }
}

__global__ void __launch_bounds__(256, 2)
k_attn(const float* __restrict__ w_t, const float* __restrict__ b_t)
{
    extern __shared__ char smc[];
    unsigned sb = smem_u32(smc);
    int mta = blockIdx.x, b = blockIdx.y;
    int tid = threadIdx.x, wid = tid >> 5, lane = tid & 31;
    float* cs = (float*)(smc + K3_CS);

    // zero INV pad rows 2-15 (both stages); never written again
    for (int st = 0; st < 2; st++)
        for (int i = tid; i < 448; i += 256)
            *(unsigned*)(smc + K3_STG + st * K3_SSZ + K3_IO + 256 + i * 4) = 0;

    int wn = wid >> 1, wm = wid & 1;      // 4 row groups x 2 col groups: 32x64 warp tile
    int rn = wn * 32, cm = wm * 64;
    bool hiA = (wn < 2);                  // A-hi warps: both planes + colsum duty
    int tjsel = wn;                       // colsum tj half for wn 0/1

    float c[2][8][4], ccs[4][4];
#pragma unroll
    for (int tj = 0; tj < 8; tj++)
#pragma unroll
        for (int q = 0; q < 4; q++) { c[0][tj][q] = 0.f; c[1][tj][q] = 0.f; }
#pragma unroll
    for (int tj = 0; tj < 4; tj++)
#pragma unroll
        for (int q = 0; q < 4; q++) ccs[tj][q] = 0.f;

    k3_issue(sb, 0, b, mta, 0, tid); CP_COMMIT();
    k3_issue(sb, 1, b, mta, 1, tid); CP_COMMIT();

    for (int ch = 0; ch < 64; ch++) {
        CP_WAIT(1);
        __syncthreads();

        unsigned sA = sb + K3_STG + (ch & 1) * K3_SSZ;
        unsigned sH = sA + K3_HO, sL = sA + K3_LO, sI = sA + K3_IO;
        bool tr = (mta > (ch >> 1));
#pragma unroll
        for (int ks = 0; ks < 4; ks++) {
            unsigned a[2][4], ainv[4];
            {
                int r0 = rn + (lane & 15);
                ldsm_x4(a[0], sA + sw128(r0, r0 * 128 + ks * 32 + (lane >> 4) * 16));
                int r1 = rn + 16 + (lane & 15);
                ldsm_x4(a[1], sA + sw128(r1, r1 * 128 + ks * 32 + (lane >> 4) * 16));
            }
            if (hiA) {
                int ri = lane & 15;
                ldsm_x4(ainv, sI + sw128(ri, ri * 128 + ks * 32 + (lane >> 4) * 16));
            }
            if (!tr) {
#pragma unroll
                for (int tj = 0; tj < 8; tj++) {
                    unsigned bb[4];
                    int br = cm + tj * 8 + (lane & 7);
                    unsigned boff = sw128(br, br * 128 + ks * 32 + ((lane >> 3) & 1) * 16);
                    if (hiA) {
                        ldsm_x4(bb, ((lane >> 4) ? sL : sH) + boff);
                        mma16816(c[0][tj], a[0], bb);     mma16816(c[1][tj], a[1], bb);
                        mma16816(c[0][tj], a[0], bb + 2); mma16816(c[1][tj], a[1], bb + 2);
                        if ((tj >> 2) == tjsel) {
                            mma16816(ccs[tj & 3], ainv, bb);
                            mma16816(ccs[tj & 3], ainv, bb + 2);
                        }
                    } else {
                        ldsm_x2(bb, sH + boff);
                        mma16816(c[0][tj], a[0], bb);     mma16816(c[1][tj], a[1], bb);
                    }
                }
            } else {
#pragma unroll
                for (int tj = 0; tj < 8; tj++) {
                    unsigned bb[4];
                    int kr = ks * 16 + (lane & 15);
                    unsigned boff = sw128(kr, kr * 256 + (cm + tj * 8) * 2);
                    if (hiA) {
                        ldsm_x4_t(bb, ((lane >> 4) ? sL : sH) + boff);
                        mma16816(c[0][tj], a[0], bb);     mma16816(c[1][tj], a[1], bb);
                        mma16816(c[0][tj], a[0], bb + 2); mma16816(c[1][tj], a[1], bb + 2);
                        if ((tj >> 2) == tjsel) {
                            mma16816(ccs[tj & 3], ainv, bb);
                            mma16816(ccs[tj & 3], ainv, bb + 2);
                        }
                    } else {
                        ldsm_x2_t(bb, sH + boff);
                        mma16816(c[0][tj], a[0], bb);     mma16816(c[1][tj], a[1], bb);
                    }
                }
            }
        }
        __syncthreads();
        if (ch + 2 < 64) { k3_issue(sb, ch & 1, b, mta, ch + 2, tid); CP_COMMIT(); }
    }

    // colsum: ccs rows 0(hi),1(lo) of inv; combine via shfl, write direct
    if (hiA) {
#pragma unroll
        for (int j = 0; j < 4; j++) {
            float v0 = ccs[j][0] + __shfl_xor_sync(0xffffffff, ccs[j][0], 4);
            float v1 = ccs[j][1] + __shfl_xor_sync(0xffffffff, ccs[j][1], 4);
            if (lane < 4) {
                int col = cm + (tjsel * 4 + j) * 8 + 2 * lane;
                cs[col]     = v0;
                cs[col + 1] = v1;
            }
        }
    }
    __syncthreads();

    // frags -> Ds [128][132]; w_t -> smem (disjoint regions)
    float* Ds  = (float*)(smc + K3_DS);
    float* Wts = (float*)(smc + K3_WTE);
#pragma unroll
    for (int ti = 0; ti < 2; ti++) {
        int r0 = rn + ti * 16 + (lane >> 2);
#pragma unroll
        for (int tj = 0; tj < 8; tj++) {
            int c0 = cm + tj * 8 + 2 * (lane & 3);
            *(float2*)&Ds[r0 * 132 + c0]       = make_float2(c[0 + 0][tj][0], c[ti][tj][1]);
            // (placeholder fixed below)
        }
    }
    // correct frag store (overwrite any placeholder writes)
#pragma unroll
    for (int ti = 0; ti < 2; ti++) {
        int r0 = rn + ti * 16 + (lane >> 2);
#pragma unroll
        for (int tj = 0; tj < 8; tj++) {
            int c0 = cm + tj * 8 + 2 * (lane & 3);
            *(float2*)&Ds[r0 * 132 + c0]       = make_float2(c[ti][tj][0], c[ti][tj][1]);
            *(float2*)&Ds[(r0 + 8) * 132 + c0] = make_float2(c[ti][tj][2], c[ti][tj][3]);
        }
    }
    for (int i = tid; i < 4096; i += 256) Wts[i] = w_t[i];
    __syncthreads();

    int o = tid >> 2, g = tid & 3;
    {   // d = x_c - (D[o]+D[o+64])/(1e-9+cs)
        const float* xcb = g_xc + (size_t)(b * 64 + o) * N_ + mta * 128;
#pragma unroll 4
        for (int k = 0; k < 32; k++) {
            int m = g * 32 + k;
            float xru = Ds[o * 132 + m] + Ds[(o + 64) * 132 + m];
            Ds[o * 132 + m] = xcb[m] - xru / (1e-9f + cs[m]);
        }
    }
    __syncthreads();

    {   // t = Wt @ d + b_t ; BN partials
        float bias = b_t[o];
        float psum = 0.f, psq = 0.f;
        float* tout = g_t + (size_t)(b * 64 + o) * N_ + mta * 128;
#pragma unroll
        for (int rep = 0; rep < 2; rep++) {
            int m0 = g * 32 + rep * 16;
            float acc[16];
#pragma unroll
            for (int j = 0; j < 16; j++) acc[j] = 0.f;
#pragma unroll 4
            for (int k = 0; k < 64; k++) {
                float w = Wts[o * 64 + k];
                const float4* dr = (const float4*)&Ds[k * 132 + m0];
#pragma unroll
                for (int q = 0; q < 4; q++) {
                    float4 d4 = dr[q];
                    acc[4*q]   += w * d4.x; acc[4*q+1] += w * d4.y;
                    acc[4*q+2] += w * d4.z; acc[4*q+3] += w * d4.w;
                }
            }
#pragma unroll
            for (int j = 0; j < 16; j += 4) {
                float t0 = acc[j] + bias, t1 = acc[j+1] + bias, t2 = acc[j+2] + bias, t3 = acc[j+3] + bias;
                *(float4*)&tout[m0 + j] = make_float4(t0, t1, t2, t3);
                psum += t0 + t1 + t2 + t3;
                psq  += t0*t0 + t1*t1 + t2*t2 + t3*t3;
            }
        }
        float* Rs = (float*)(smc + K3_RS);
        float* Rq = (float*)(smc + K3_RQ);
        Rs[o * 4 + g] = psum;
        Rq[o * 4 + g] = psq;
        __syncthreads();
        if (tid < 64) {
            float s = Rs[tid*4] + Rs[tid*4+1] + Rs[tid*4+2] + Rs[tid*4+3];
            float q = Rq[tid*4] + Rq[tid*4+1] + Rq[tid*4+2] + Rq[tid*4+3];
            int blk = b * 32 + mta;
            g_part[tid * 256 + blk]            = s;
            g_part[64 * 256 + tid * 256 + blk] = q;
        }
    }
}

// ================= K5: BN stats =================
__global__ void k_bnstats(const float* __restrict__ gamma, const float* __restrict__ beta)
{
    int c = threadIdx.x;
    if (c >= 64) return;
    float s = 0.f, q = 0.f;
    for (int j = 0; j < 256; j++) {
        s += g_part[c * 256 + j];
        q += g_part[64 * 256 + c * 256 + j];
    }
    const float invN = 1.0f / 32768.0f;
    float mean = s * invN;
    float var  = q * invN - mean * mean;
    float sc = gamma[c] * rsqrtf(var + 1e-5f);
    g_bn[c]      = sc;
    g_bn[64 + c] = beta[c] - mean * sc;
}

// ================= K6: out = x_c + relu(scale*t + shift) =================
__global__ void k_final(float* __restrict__ out)
{
    int i4 = blockIdx.x * 256 + threadIdx.x;
    if (i4 >= B_ * C2_ * (N_ / 4)) return;
    int ch = (i4 >> 10) & 63;
    float sc = g_bn[ch], sh = g_bn[64 + ch];
    float4 t  = ((const float4*)g_t)[i4];
    float4 xc = ((const float4*)g_xc)[i4];
    float4 r;
    r.x = xc.x + fmaxf(0.f, sc * t.x + sh);
    r.y = xc.y + fmaxf(0.f, sc * t.y + sh);
    r.z = xc.z + fmaxf(0.f, sc * t.z + sh);
    r.w = xc.w + fmaxf(0.f, sc * t.w + sh);
    ((float4*)out)[i4] = r;
}

// ================= launch =================
extern "C" void kernel_launch(void* const* d_in, const int* in_sizes, int n_in,
                              void* d_out, int out_size)
{
    const float* x     = (const float*)d_in[0];
    const float* w_qk  = (const float*)d_in[1];
    const float* w_v   = (const float*)d_in[2];
    const float* b_v   = (const float*)d_in[3];
    const float* w_x   = (const float*)d_in[4];
    const float* w_t   = (const float*)d_in[5];
    const float* b_t   = (const float*)d_in[6];
    const float* gamma = (const float*)d_in[7];
    const float* beta  = (const float*)d_in[8];
    float* out = (float*)d_out;

    cudaFuncSetAttribute(k_proj,   cudaFuncAttributeMaxDynamicSharedMemorySize, P_SMEM);
    cudaFuncSetAttribute(k_energy, cudaFuncAttributeMaxDynamicSharedMemorySize, K2_SMEM);
    cudaFuncSetAttribute(k_attn,   cudaFuncAttributeMaxDynamicSharedMemorySize, K3_SMEM);

    k_proj    <<<dim3(32, 8), 256, P_SMEM>>>(x, w_qk, w_v, b_v, w_x);
    k_energy  <<<dim3(528, 8), 256, K2_SMEM>>>();
    k_rowav   <<<128, 256>>>();
    k_attn    <<<dim3(32, 8), 256, K3_SMEM>>>(w_t, b_t);
    k_bnstats <<<1, 64>>>(gamma, beta);
    k_final   <<<2048, 256>>>(out);
}

// round 14
// speedup vs baseline: 1.2965x; 1.2965x over previous
#include <cuda_runtime.h>
#include <cuda_bf16.h>
#include <math.h>

#define B_  8
#define C_  128
#define N_  4096
#define C2_ 64

// ---------------- scratch ----------------
__device__ __align__(16) __nv_bfloat16 g_qs[B_*N_*128];    // [b][n][k] k:0-63 hi, 64-127 lo
__device__ __align__(16) float g_v [B_*C2_*N_];
__device__ __align__(16) float g_xc[B_*C2_*N_];
__device__ __align__(16) float g_rspart[B_*32*32*128];     // rowsum partials (b,nt,mt,row)
__device__ __align__(16) __nv_bfloat16 g_invsbf[B_*2*N_];  // [b][hi/lo][n]
__device__ __align__(16) __nv_bfloat16 g_av[B_*128*N_];    // [b][r][n] r:0-63 hi(v*invs), 64-127 lo
__device__ __align__(16) float g_t [B_*C2_*N_];
__device__ __align__(16) float g_part[2*64*256];
__device__ __align__(16) float g_bn[128];
__device__ __align__(16) __nv_bfloat16 g_ph[(size_t)B_*N_*N_];  // hi plane of exp(E), UPPER tiles only
__device__ __align__(16) __nv_bfloat16 g_pl[(size_t)B_*N_*N_];  // lo plane, UPPER tiles only

// ---------------- helpers ----------------
__device__ __forceinline__ unsigned smem_u32(const void* p){
    unsigned a; asm("{ .reg .u64 t; cvta.to.shared.u64 t, %1; cvt.u32.u64 %0, t; }" : "=r"(a) : "l"(p)); return a;
}
__device__ __forceinline__ void ldsm_x4(unsigned* r, unsigned addr){
    asm volatile("ldmatrix.sync.aligned.m8n8.x4.shared.b16 {%0,%1,%2,%3}, [%4];"
        : "=r"(r[0]), "=r"(r[1]), "=r"(r[2]), "=r"(r[3]) : "r"(addr));
}
__device__ __forceinline__ void ldsm_x4_t(unsigned* r, unsigned addr){
    asm volatile("ldmatrix.sync.aligned.m8n8.x4.trans.shared.b16 {%0,%1,%2,%3}, [%4];"
        : "=r"(r[0]), "=r"(r[1]), "=r"(r[2]), "=r"(r[3]) : "r"(addr));
}
__device__ __forceinline__ void mma16816(float* c, const unsigned* a, const unsigned* b){
    asm volatile("mma.sync.aligned.m16n8k16.row.col.f32.bf16.bf16.f32 "
        "{%0,%1,%2,%3}, {%4,%5,%6,%7}, {%8,%9}, {%0,%1,%2,%3};"
        : "+f"(c[0]), "+f"(c[1]), "+f"(c[2]), "+f"(c[3])
        : "r"(a[0]), "r"(a[1]), "r"(a[2]), "r"(a[3]), "r"(b[0]), "r"(b[1]));
}
__device__ __forceinline__ void cp16(unsigned s, const void* g){
    asm volatile("{ .reg .u64 gp; cvta.to.global.u64 gp, %1; cp.async.cg.shared.global [%0], [gp], 16; }"
        :: "r"(s), "l"(g));
}
#define CP_COMMIT() asm volatile("cp.async.commit_group;" ::: "memory")
#define CP_WAIT(n)  asm volatile("cp.async.wait_group %0;" :: "n"(n) : "memory")

__device__ __forceinline__ unsigned packbf(__nv_bfloat16 a, __nv_bfloat16 b){
    return (unsigned)__bfloat16_as_ushort(a) | ((unsigned)__bfloat16_as_ushort(b) << 16);
}

// ================= K1: projections via split-bf16 HMMA =================
#define P_WH 0
#define P_WL 52224
#define P_XH 104448
#define P_XL 139264
#define P_SMEM 174080
__global__ void __launch_bounds__(256)
k_proj(const float* __restrict__ x, const float* __restrict__ w_qk,
       const float* __restrict__ w_v, const float* __restrict__ b_v,
       const float* __restrict__ w_x)
{
    extern __shared__ char smc[];
    unsigned sb = smem_u32(smc);
    int b = blockIdx.y, nt = blockIdx.x;
    int tid = threadIdx.x, wid = tid >> 5, lane = tid & 31;

    unsigned short* WH = (unsigned short*)(smc + P_WH);
    unsigned short* WL = (unsigned short*)(smc + P_WL);
    for (int i = tid; i < 24576; i += 256) {
        float wv = (i < 8192) ? w_qk[i] : (i < 16384 ? w_v[i - 8192] : w_x[i - 16384]);
        int row = i >> 7, cc = i & 127;
        __nv_bfloat16 h = __float2bfloat16(wv);
        __nv_bfloat16 l = __float2bfloat16(wv - __bfloat162float(h));
        WH[row * 136 + cc] = __bfloat16_as_ushort(h);
        WL[row * 136 + cc] = __bfloat16_as_ushort(l);
    }
    unsigned short* XH = (unsigned short*)(smc + P_XH);
    unsigned short* XL = (unsigned short*)(smc + P_XL);
    const float* xp = x + (size_t)(b * C_) * N_ + nt * 128;
    for (int i = tid; i < 16384; i += 256) {
        int c = i >> 7, n = i & 127;
        float v = xp[(size_t)c * N_ + n];
        __nv_bfloat16 h = __float2bfloat16(v);
        __nv_bfloat16 l = __float2bfloat16(v - __bfloat162float(h));
        XH[c * 136 + n] = __bfloat16_as_ushort(h);
        XL[c * 136 + n] = __bfloat16_as_ushort(l);
    }
    __syncthreads();

    int wn = wid >> 1, wm = wid & 1;
    int rm = wn * 48, cn = wm * 64;
    float c[3][8][4];
#pragma unroll
    for (int ti = 0; ti < 3; ti++)
#pragma unroll
        for (int tj = 0; tj < 8; tj++)
#pragma unroll
            for (int q = 0; q < 4; q++) c[ti][tj][q] = 0.f;

#pragma unroll
    for (int p = 0; p < 3; p++) {
        unsigned wa = sb + ((p == 2) ? P_WL : P_WH);
        unsigned xb = sb + ((p == 1) ? P_XL : P_XH);
#pragma unroll
        for (int ks = 0; ks < 8; ks++) {
            unsigned a[3][4];
#pragma unroll
            for (int ti = 0; ti < 3; ti++)
                ldsm_x4(a[ti], wa + (rm + ti * 16 + (lane & 15)) * 272 + ks * 32 + (lane >> 4) * 16);
#pragma unroll
            for (int tjp = 0; tjp < 4; tjp++) {
                unsigned bb[4];
                ldsm_x4_t(bb, xb + (ks * 16 + (lane & 15)) * 272
                              + (cn + tjp * 16 + ((lane >> 4) << 3)) * 2);
#pragma unroll
                for (int ti = 0; ti < 3; ti++) {
                    mma16816(c[ti][2 * tjp],     a[ti], bb);
                    mma16816(c[ti][2 * tjp + 1], a[ti], bb + 2);
                }
            }
        }
    }
    __syncthreads();

    unsigned short* qstage = (unsigned short*)(smc + P_XH);
#pragma unroll
    for (int ti = 0; ti < 3; ti++) {
        int r0 = rm + ti * 16;
        int r = r0 + (lane >> 2);
#pragma unroll
        for (int tj = 0; tj < 8; tj++) {
            int c0 = cn + tj * 8 + 2 * (lane & 3);
            float v0 = c[ti][tj][0], v1 = c[ti][tj][1], v2 = c[ti][tj][2], v3 = c[ti][tj][3];
            if (r0 < 64) {
                __nv_bfloat16 h0 = __float2bfloat16(v0), h1 = __float2bfloat16(v1);
                __nv_bfloat16 h2 = __float2bfloat16(v2), h3 = __float2bfloat16(v3);
                qstage[c0 * 128 + r]            = __bfloat16_as_ushort(h0);
                qstage[c0 * 128 + 64 + r]       = __bfloat16_as_ushort(__float2bfloat16(v0 - __bfloat162float(h0)));
                qstage[(c0 + 1) * 128 + r]      = __bfloat16_as_ushort(h1);
                qstage[(c0 + 1) * 128 + 64 + r] = __bfloat16_as_ushort(__float2bfloat16(v1 - __bfloat162float(h1)));
                qstage[c0 * 128 + r + 8]            = __bfloat16_as_ushort(h2);
                qstage[c0 * 128 + 64 + r + 8]       = __bfloat16_as_ushort(__float2bfloat16(v2 - __bfloat162float(h2)));
                qstage[(c0 + 1) * 128 + r + 8]      = __bfloat16_as_ushort(h3);
                qstage[(c0 + 1) * 128 + 64 + r + 8] = __bfloat16_as_ushort(__float2bfloat16(v3 - __bfloat162float(h3)));
            } else if (r0 < 128) {
                float ba = b_v[r - 64], bb2 = b_v[r - 56];
                *(float2*)&g_v[(size_t)(b * 64 + r - 64) * N_ + nt * 128 + c0] = make_float2(v0 + ba, v1 + ba);
                *(float2*)&g_v[(size_t)(b * 64 + r - 56) * N_ + nt * 128 + c0] = make_float2(v2 + bb2, v3 + bb2);
            } else {
                *(float2*)&g_xc[(size_t)(b * 64 + r - 128) * N_ + nt * 128 + c0] = make_float2(v0, v1);
                *(float2*)&g_xc[(size_t)(b * 64 + r - 120) * N_ + nt * 128 + c0] = make_float2(v2, v3);
            }
        }
    }
    __syncthreads();
    for (int i = tid; i < 2048; i += 256) {
        int row = i >> 4, cc = i & 15;
        ((uint4*)(g_qs + (size_t)(b * N_ + nt * 128 + row) * 128))[cc] =
            ((const uint4*)(qstage + row * 128))[cc];
    }
}

// ================= K2: symmetric E=Q^T Q, P=exp(E) upper tiles only, rowsums both sides ===
#define K2_AS 0
#define K2_BS 34816
#define K2_RED 0
#define K2_RDT 4096
#define K2_SMEM 69632
__global__ void __launch_bounds__(256, 2)
k_energy()
{
    extern __shared__ char smc[];
    unsigned sb = smem_u32(smc);
    int b = blockIdx.y;
    int tid = threadIdx.x, wid = tid >> 5, lane = tid & 31;

    int u = blockIdx.x, nt = 0;
    while (u >= 32 - nt) { u -= 32 - nt; nt++; }
    int mt = nt + u;

    {
        const uint4* asrc = (const uint4*)(g_qs + (size_t)(b * N_ + nt * 128) * 128);
        const uint4* bsrc = (const uint4*)(g_qs + (size_t)(b * N_ + mt * 128) * 128);
        for (int i = tid; i < 2048; i += 256) {
            int row = i >> 4, cc = i & 15;
            *(uint4*)(smc + K2_AS + row * 272 + cc * 16) = asrc[i];
            *(uint4*)(smc + K2_BS + row * 272 + cc * 16) = bsrc[i];
        }
    }
    __syncthreads();

    int wn = wid >> 1, wm = wid & 1;
    int rn = wn * 32, cm = wm * 64;
    float c[2][8][4];
#pragma unroll
    for (int ti = 0; ti < 2; ti++)
#pragma unroll
        for (int tj = 0; tj < 8; tj++)
#pragma unroll
            for (int q = 0; q < 4; q++) c[ti][tj][q] = 0.f;

    const int qa[3] = {0, 0, 1}, qb[3] = {0, 1, 0};
#pragma unroll
    for (int s = 0; s < 12; s++) {
        int grp = s >> 2, km = (s & 3) * 32;
        int ka = qa[grp] * 128 + km, kb = qb[grp] * 128 + km;
        unsigned a[2][4];
#pragma unroll
        for (int ti = 0; ti < 2; ti++)
            ldsm_x4(a[ti], sb + K2_AS + (rn + ti * 16 + (lane & 15)) * 272 + ka + (lane >> 4) * 16);
#pragma unroll
        for (int tjp = 0; tjp < 4; tjp++) {
            unsigned bb[4];
            ldsm_x4(bb, sb + K2_BS + (cm + tjp * 16 + ((lane >> 4) << 3) + (lane & 7)) * 272
                        + kb + ((lane >> 3) & 1) * 16);
            mma16816(c[0][2*tjp],   a[0], bb);     mma16816(c[1][2*tjp],   a[1], bb);
            mma16816(c[0][2*tjp+1], a[0], bb + 2); mma16816(c[1][2*tjp+1], a[1], bb + 2);
        }
    }

    bool offd = (mt != nt);
    float rsA[2] = {0.f, 0.f}, rsB[2] = {0.f, 0.f};
    float colp0[8], colp1[8];
#pragma unroll
    for (int tj = 0; tj < 8; tj++) { colp0[tj] = 0.f; colp1[tj] = 0.f; }
    size_t prow = (size_t)(b * N_ + nt * 128) * N_ + mt * 128;
#pragma unroll
    for (int ti = 0; ti < 2; ti++) {
        int r0 = rn + ti * 16 + (lane >> 2);
#pragma unroll
        for (int tj = 0; tj < 8; tj++) {
            int c0 = cm + tj * 8 + 2 * (lane & 3);
            float p0 = __expf(c[ti][tj][0]), p1 = __expf(c[ti][tj][1]);
            float p2 = __expf(c[ti][tj][2]), p3 = __expf(c[ti][tj][3]);
            rsA[ti] += p0 + p1;  rsB[ti] += p2 + p3;
            colp0[tj] += p0 + p2; colp1[tj] += p1 + p3;
            __nv_bfloat16 h0 = __float2bfloat16(p0), h1 = __float2bfloat16(p1);
            __nv_bfloat16 h2 = __float2bfloat16(p2), h3 = __float2bfloat16(p3);
            __nv_bfloat16 l0 = __float2bfloat16(p0 - __bfloat162float(h0));
            __nv_bfloat16 l1 = __float2bfloat16(p1 - __bfloat162float(h1));
            __nv_bfloat16 l2 = __float2bfloat16(p2 - __bfloat162float(h2));
            __nv_bfloat16 l3 = __float2bfloat16(p3 - __bfloat162float(h3));
            size_t ba = prow + (size_t)r0 * N_ + c0;
            size_t bc = ba + (size_t)8 * N_;
            *(unsigned*)(g_ph + ba) = packbf(h0, h1);
            *(unsigned*)(g_pl + ba) = packbf(l0, l1);
            *(unsigned*)(g_ph + bc) = packbf(h2, h3);
            *(unsigned*)(g_pl + bc) = packbf(l2, l3);
        }
    }
    if (offd) {
#pragma unroll
        for (int tj = 0; tj < 8; tj++) {
            colp0[tj] += __shfl_xor_sync(0xffffffff, colp0[tj], 4);
            colp0[tj] += __shfl_xor_sync(0xffffffff, colp0[tj], 8);
            colp0[tj] += __shfl_xor_sync(0xffffffff, colp0[tj], 16);
            colp1[tj] += __shfl_xor_sync(0xffffffff, colp1[tj], 4);
            colp1[tj] += __shfl_xor_sync(0xffffffff, colp1[tj], 8);
            colp1[tj] += __shfl_xor_sync(0xffffffff, colp1[tj], 16);
        }
    }
    __syncthreads();

    float* red  = (float*)(smc + K2_RED);
    float* redT = (float*)(smc + K2_RDT);
#pragma unroll
    for (int ti = 0; ti < 2; ti++) {
        int r0 = rn + ti * 16 + (lane >> 2);
        red[r0 * 8 + wm * 4 + (lane & 3)]       = rsA[ti];
        red[(r0 + 8) * 8 + wm * 4 + (lane & 3)] = rsB[ti];
    }
    if (offd && lane < 4) {
#pragma unroll
        for (int tj = 0; tj < 8; tj++) {
            redT[wn * 128 + cm + tj * 8 + 2 * lane]     = colp0[tj];
            redT[wn * 128 + cm + tj * 8 + 2 * lane + 1] = colp1[tj];
        }
    }
    __syncthreads();
    if (tid < 128) {
        float s = 0.f;
#pragma unroll
        for (int j = 0; j < 8; j++) s += red[tid * 8 + j];
        g_rspart[((size_t)(b * 32 + nt) * 32 + mt) * 128 + tid] = s;
        if (offd) {
            float st = redT[tid] + redT[128 + tid] + redT[256 + tid] + redT[384 + tid];
            g_rspart[((size_t)(b * 32 + mt) * 32 + nt) * 128 + tid] = st;
        }
    }
}

// ================= K2.5: rowsum reduce -> invsbf, Av = v*inv split (merged) =================
__global__ void k_rowav()
{
    int idx = blockIdx.x * 256 + threadIdx.x;
    int b = idx >> 12, n = idx & 4095;
    float s = 0.f;
    const float* p = g_rspart + ((size_t)(b * 32 + (n >> 7)) * 32) * 128 + (n & 127);
#pragma unroll
    for (int mt = 0; mt < 32; mt++) s += p[mt * 128];
    float inv = 1.0f / s;
    __nv_bfloat16 ih = __float2bfloat16(inv);
    g_invsbf[(b * 2 + 0) * N_ + n] = ih;
    g_invsbf[(b * 2 + 1) * N_ + n] = __float2bfloat16(inv - __bfloat162float(ih));
    const float* vs = g_v + (size_t)(b * 64) * N_ + n;
    __nv_bfloat16* avh = g_av + (size_t)(b * 128) * N_ + n;
#pragma unroll 4
    for (int o = 0; o < 64; o++) {
        float a = vs[(size_t)o * N_] * inv;
        __nv_bfloat16 h = __float2bfloat16(a);
        avh[(size_t)o * N_]        = h;
        avh[(size_t)(o + 64) * N_] = __float2bfloat16(a - __bfloat162float(h));
    }
}

// ================= K3: D = Ah@(Ph+Pl) + Al@Ph; 512 thr, 16 warp-tiles, 3-stage cp.async ===
// grid (16, 8); each block: 2 mt tiles of 128 cols. Warp: 16 hi-rows + 16 lo-rows x 32 cols.
#define K3T      512
#define K3_WT    0           // 16384
#define K3_CS2   16384       // [4][128] f32
#define K3_CS    18432       // [128] f32
#define K3_STG   21504
#define K3_SSZ   57600       // A 18432 | H 18432 | L 18432 | INV 2304
#define K3_RED   (K3_STG + 69632)    // after Ds(67584): [64][8]x2 f32 = 4096
#define K3_SMEM  (21504 + 3*57600)
__device__ __forceinline__ void k3_issue(unsigned sb, int st, int b, int mta, int ch, int tid)
{
    unsigned s0 = sb + K3_STG + st * K3_SSZ;
    int nb = ch << 6;
    bool tr = (mta > (ch >> 1));
    const __nv_bfloat16* asrc = g_av + (size_t)b * 128 * N_ + nb;
    const __nv_bfloat16 *hsrc, *lsrc;
    if (!tr) {
        hsrc = g_ph + ((size_t)(b * N_ + mta * 128)) * N_ + nb;
        lsrc = g_pl + ((size_t)(b * N_ + mta * 128)) * N_ + nb;
    } else {
        hsrc = g_ph + ((size_t)(b * N_ + nb)) * N_ + mta * 128;
        lsrc = g_pl + ((size_t)(b * N_ + nb)) * N_ + mta * 128;
    }
    for (int i = tid; i < 1024; i += K3T) {
        int ar = i >> 3, ac = i & 7;
        cp16(s0 + ar * 144 + ac * 16, asrc + (size_t)ar * N_ + ac * 8);
        if (!tr) {
            cp16(s0 + 18432 + ar * 144 + ac * 16, hsrc + (size_t)ar * N_ + ac * 8);
            cp16(s0 + 36864 + ar * 144 + ac * 16, lsrc + (size_t)ar * N_ + ac * 8);
        } else {
            int rr = i >> 4, cc = i & 15;
            cp16(s0 + 18432 + rr * 272 + cc * 16, hsrc + (size_t)rr * N_ + cc * 8);
            cp16(s0 + 36864 + rr * 272 + cc * 16, lsrc + (size_t)rr * N_ + cc * 8);
        }
    }
    if (tid < 16) {
        int row = tid >> 3, cc = tid & 7;
        cp16(s0 + 55296 + row * 144 + cc * 16,
             g_invsbf + (size_t)(b * 2 + row) * N_ + nb + cc * 8);
    }
}

__global__ void __launch_bounds__(K3T)
k_attn(const float* __restrict__ w_t, const float* __restrict__ b_t)
{
    extern __shared__ char smc[];
    unsigned sb = smem_u32(smc);
    int b = blockIdx.y;
    int tid = threadIdx.x, wid = tid >> 5, lane = tid & 31;
    float* Wts = (float*)(smc + K3_WT);
    float* cs2 = (float*)(smc + K3_CS2);
    float* cs  = (float*)(smc + K3_CS);

    for (int i = tid; i < 4096; i += K3T) Wts[i] = w_t[i];
    for (int st = 0; st < 3; st++)
        for (int i = tid; i < 504; i += K3T)
            *(unsigned*)(smc + K3_STG + st * K3_SSZ + 55296 + 288 + i * 4) = 0;

    int wn = wid >> 2, wm = wid & 3;        // 16 warps: 4 row groups x 4 col groups
    int rh = wn * 16, rl = 64 + wn * 16;    // each warp: 16 hi-rows + 16 lo-rows
    int cm = wm * 32;

#pragma unroll 1
    for (int half = 0; half < 2; half++) {
        int mta = blockIdx.x * 2 + half;
        float c[2][4][4], ccs[4][4];
#pragma unroll
        for (int tj = 0; tj < 4; tj++) {
#pragma unroll
            for (int q = 0; q < 4; q++) { c[0][tj][q] = 0.f; c[1][tj][q] = 0.f; ccs[tj][q] = 0.f; }
        }
        __syncthreads();
        k3_issue(sb, 0, b, mta, 0, tid); CP_COMMIT();
        k3_issue(sb, 1, b, mta, 1, tid); CP_COMMIT();

        for (int ch = 0; ch < 64; ch++) {
            if (ch + 2 < 64) CP_WAIT(1); else CP_WAIT(0);
            __syncthreads();
            if (ch + 2 < 64) { k3_issue(sb, (ch + 2) % 3, b, mta, ch + 2, tid); CP_COMMIT(); }

            unsigned sA = sb + K3_STG + (ch % 3) * K3_SSZ;
            unsigned sH = sA + 18432, sL = sA + 36864, sI = sA + 55296;
            bool tr = (mta > (ch >> 1));
            if (!tr) {
#pragma unroll
                for (int ks = 0; ks < 4; ks++) {
                    unsigned a[2][4], ainv[4];
                    ldsm_x4(a[0], sA + (rh + (lane & 15)) * 144 + ks * 32 + (lane >> 4) * 16);
                    ldsm_x4(a[1], sA + (rl + (lane & 15)) * 144 + ks * 32 + (lane >> 4) * 16);
                    bool mine = (ks == wn);
                    if (mine) ldsm_x4(ainv, sI + (lane & 15) * 144 + ks * 32 + (lane >> 4) * 16);
#pragma unroll
                    for (int tj = 0; tj < 4; tj++) {
                        unsigned bb[4];     // bh in [0,1], bl in [2,3]
                        unsigned boff = (cm + tj * 8 + (lane & 7)) * 144 + ks * 32 + ((lane >> 3) & 1) * 16;
                        ldsm_x4(bb, ((lane >> 4) ? sL : sH) + boff);
                        mma16816(c[0][tj], a[0], bb);      mma16816(c[1][tj], a[1], bb);
                        mma16816(c[0][tj], a[0], bb + 2);  // Al@Pl dropped (2^-17 rel)
                        if (mine) { mma16816(ccs[tj], ainv, bb); mma16816(ccs[tj], ainv, bb + 2); }
                    }
                }
            } else {
#pragma unroll
                for (int ks = 0; ks < 4; ks++) {
                    unsigned a[2][4], ainv[4];
                    ldsm_x4(a[0], sA + (rh + (lane & 15)) * 144 + ks * 32 + (lane >> 4) * 16);
                    ldsm_x4(a[1], sA + (rl + (lane & 15)) * 144 + ks * 32 + (lane >> 4) * 16);
                    bool mine = (ks == wn);
                    if (mine) ldsm_x4(ainv, sI + (lane & 15) * 144 + ks * 32 + (lane >> 4) * 16);
#pragma unroll
                    for (int tj = 0; tj < 4; tj++) {
                        unsigned bb[4];
                        unsigned boff = (ks * 16 + (lane & 15)) * 272 + (cm + tj * 8) * 2;
                        ldsm_x4_t(bb, ((lane >> 4) ? sL : sH) + boff);
                        mma16816(c[0][tj], a[0], bb);      mma16816(c[1][tj], a[1], bb);
                        mma16816(c[0][tj], a[0], bb + 2);  // Al@Pl dropped
                        if (mine) { mma16816(ccs[tj], ainv, bb); mma16816(ccs[tj], ainv, bb + 2); }
                    }
                }
            }
        }
#pragma unroll
        for (int tj = 0; tj < 4; tj++) {
            float v0 = ccs[tj][0] + __shfl_xor_sync(0xffffffff, ccs[tj][0], 4);
            float v1 = ccs[tj][1] + __shfl_xor_sync(0xffffffff, ccs[tj][1], 4);
            if (lane < 4) {
                cs2[wn * 128 + cm + tj * 8 + 2 * lane]     = v0;
                cs2[wn * 128 + cm + tj * 8 + 2 * lane + 1] = v1;
            }
        }
        __syncthreads();
        if (tid < 128)
            cs[tid] = cs2[tid] + cs2[128 + tid] + cs2[256 + tid] + cs2[384 + tid];
        __syncthreads();

        float* Ds = (float*)(smc + K3_STG);
#pragma unroll
        for (int ti = 0; ti < 2; ti++) {
            int r0 = (ti == 0 ? rh : rl) + (lane >> 2);
#pragma unroll
            for (int tj = 0; tj < 4; tj++) {
                int c0 = cm + tj * 8 + 2 * (lane & 3);
                *(float2*)&Ds[r0 * 132 + c0]       = make_float2(c[ti][tj][0], c[ti][tj][1]);
                *(float2*)&Ds[(r0 + 8) * 132 + c0] = make_float2(c[ti][tj][2], c[ti][tj][3]);
            }
        }
        __syncthreads();

        int o = tid >> 3, g = tid & 7;      // 64 channels x 8 col-groups of 16
        {
            const float* xcb = g_xc + (size_t)(b * 64 + o) * N_ + mta * 128;
#pragma unroll 4
            for (int k = 0; k < 16; k++) {
                int m = g * 16 + k;
                float xru = Ds[o * 132 + m] + Ds[(o + 64) * 132 + m];
                Ds[o * 132 + m] = xcb[m] - xru / (1e-9f + cs[m]);
            }
        }
        __syncthreads();

        {
            float bias = b_t[o];
            float psum = 0.f, psq = 0.f;
            float* tout = g_t + (size_t)(b * 64 + o) * N_ + mta * 128;
            int m0 = g * 16;
            float acc[16];
#pragma unroll
            for (int j = 0; j < 16; j++) acc[j] = 0.f;
#pragma unroll 4
            for (int k = 0; k < 64; k++) {
                float w = Wts[o * 64 + k];
                const float4* dr = (const float4*)&Ds[k * 132 + m0];
#pragma unroll
                for (int q = 0; q < 4; q++) {
                    float4 d4 = dr[q];
                    acc[4*q]   += w * d4.x; acc[4*q+1] += w * d4.y;
                    acc[4*q+2] += w * d4.z; acc[4*q+3] += w * d4.w;
                }
            }
#pragma unroll
            for (int j = 0; j < 16; j += 4) {
                float t0 = acc[j] + bias, t1 = acc[j+1] + bias, t2 = acc[j+2] + bias, t3 = acc[j+3] + bias;
                *(float4*)&tout[m0 + j] = make_float4(t0, t1, t2, t3);
                psum += t0 + t1 + t2 + t3;
                psq  += t0*t0 + t1*t1 + t2*t2 + t3*t3;
            }
            float* Rs = (float*)(smc + K3_RED);
            float* Rq = Rs + 512;
            Rs[o * 8 + g] = psum;
            Rq[o * 8 + g] = psq;
            __syncthreads();
            if (tid < 64) {
                float s = 0.f, q = 0.f;
#pragma unroll
                for (int j = 0; j < 8; j++) { s += Rs[tid * 8 + j]; q += Rq[tid * 8 + j]; }
                int blk = b * 32 + mta;
                g_part[tid * 256 + blk]            = s;
                g_part[64 * 256 + tid * 256 + blk] = q;
            }
        }
    }
}

// ================= K5: BN stats =================
__global__ void k_bnstats(const float* __restrict__ gamma, const float* __restrict__ beta)
{
    int c = threadIdx.x;
    if (c >= 64) return;
    float s = 0.f, q = 0.f;
    for (int j = 0; j < 256; j++) {
        s += g_part[c * 256 + j];
        q += g_part[64 * 256 + c * 256 + j];
    }
    const float invN = 1.0f / 32768.0f;
    float mean = s * invN;
    float var  = q * invN - mean * mean;
    float sc = gamma[c] * rsqrtf(var + 1e-5f);
    g_bn[c]      = sc;
    g_bn[64 + c] = beta[c] - mean * sc;
}

// ================= K6: out = x_c + relu(scale*t + shift) =================
__global__ void k_final(float* __restrict__ out)
{
    int i4 = blockIdx.x * 256 + threadIdx.x;
    if (i4 >= B_ * C2_ * (N_ / 4)) return;
    int ch = (i4 >> 10) & 63;
    float sc = g_bn[ch], sh = g_bn[64 + ch];
    float4 t  = ((const float4*)g_t)[i4];
    float4 xc = ((const float4*)g_xc)[i4];
    float4 r;
    r.x = xc.x + fmaxf(0.f, sc * t.x + sh);
    r.y = xc.y + fmaxf(0.f, sc * t.y + sh);
    r.z = xc.z + fmaxf(0.f, sc * t.z + sh);
    r.w = xc.w + fmaxf(0.f, sc * t.w + sh);
    ((float4*)out)[i4] = r;
}

// ================= launch =================
extern "C" void kernel_launch(void* const* d_in, const int* in_sizes, int n_in,
                              void* d_out, int out_size)
{
    const float* x     = (const float*)d_in[0];
    const float* w_qk  = (const float*)d_in[1];
    const float* w_v   = (const float*)d_in[2];
    const float* b_v   = (const float*)d_in[3];
    const float* w_x   = (const float*)d_in[4];
    const float* w_t   = (const float*)d_in[5];
    const float* b_t   = (const float*)d_in[6];
    const float* gamma = (const float*)d_in[7];
    const float* beta  = (const float*)d_in[8];
    float* out = (float*)d_out;

    cudaFuncSetAttribute(k_proj,   cudaFuncAttributeMaxDynamicSharedMemorySize, P_SMEM);
    cudaFuncSetAttribute(k_energy, cudaFuncAttributeMaxDynamicSharedMemorySize, K2_SMEM);
    cudaFuncSetAttribute(k_attn,   cudaFuncAttributeMaxDynamicSharedMemorySize, K3_SMEM);

    k_proj    <<<dim3(32, 8), 256, P_SMEM>>>(x, w_qk, w_v, b_v, w_x);
    k_energy  <<<dim3(528, 8), 256, K2_SMEM>>>();
    k_rowav   <<<128, 256>>>();
    k_attn    <<<dim3(16, 8), K3T, K3_SMEM>>>(w_t, b_t);
    k_bnstats <<<1, 64>>>(gamma, beta);
    k_final   <<<2048, 256>>>(out);
}

// round 15
// speedup vs baseline: 1.3306x; 1.0263x over previous
#include <cuda_runtime.h>
#include <cuda_bf16.h>
#include <math.h>

#define B_  8
#define C_  128
#define N_  4096
#define C2_ 64

// ---------------- scratch ----------------
__device__ __align__(16) __nv_bfloat16 g_qs[B_*N_*128];    // [b][n][k] k:0-63 hi, 64-127 lo
__device__ __align__(16) float g_v [B_*C2_*N_];
__device__ __align__(16) float g_xc[B_*C2_*N_];
__device__ __align__(16) float g_rspart[B_*32*32*128];     // rowsum partials (b,nt,mt,row)
__device__ __align__(16) __nv_bfloat16 g_invsbf[B_*2*N_];  // [b][hi/lo][n]
__device__ __align__(16) __nv_bfloat16 g_av[B_*128*N_];    // [b][r][n] r:0-63 hi(v*invs), 64-127 lo
__device__ __align__(16) float g_t [B_*C2_*N_];
__device__ __align__(16) float g_part[2*64*256];
__device__ __align__(16) float g_bn[128];
__device__ __align__(16) __nv_bfloat16 g_ph[(size_t)B_*N_*N_];  // hi plane of exp(E), UPPER tiles only
__device__ __align__(16) __nv_bfloat16 g_pl[(size_t)B_*N_*N_];  // lo plane, UPPER tiles only

// ---------------- helpers ----------------
__device__ __forceinline__ unsigned smem_u32(const void* p){
    unsigned a; asm("{ .reg .u64 t; cvta.to.shared.u64 t, %1; cvt.u32.u64 %0, t; }" : "=r"(a) : "l"(p)); return a;
}
__device__ __forceinline__ void ldsm_x4(unsigned* r, unsigned addr){
    asm volatile("ldmatrix.sync.aligned.m8n8.x4.shared.b16 {%0,%1,%2,%3}, [%4];"
        : "=r"(r[0]), "=r"(r[1]), "=r"(r[2]), "=r"(r[3]) : "r"(addr));
}
__device__ __forceinline__ void ldsm_x4_t(unsigned* r, unsigned addr){
    asm volatile("ldmatrix.sync.aligned.m8n8.x4.trans.shared.b16 {%0,%1,%2,%3}, [%4];"
        : "=r"(r[0]), "=r"(r[1]), "=r"(r[2]), "=r"(r[3]) : "r"(addr));
}
__device__ __forceinline__ void mma16816(float* c, const unsigned* a, const unsigned* b){
    asm volatile("mma.sync.aligned.m16n8k16.row.col.f32.bf16.bf16.f32 "
        "{%0,%1,%2,%3}, {%4,%5,%6,%7}, {%8,%9}, {%0,%1,%2,%3};"
        : "+f"(c[0]), "+f"(c[1]), "+f"(c[2]), "+f"(c[3])
        : "r"(a[0]), "r"(a[1]), "r"(a[2]), "r"(a[3]), "r"(b[0]), "r"(b[1]));
}
__device__ __forceinline__ void cp16(unsigned s, const void* g){
    asm volatile("{ .reg .u64 gp; cvta.to.global.u64 gp, %1; cp.async.cg.shared.global [%0], [gp], 16; }"
        :: "r"(s), "l"(g));
}
#define CP_COMMIT() asm volatile("cp.async.commit_group;" ::: "memory")
#define CP_WAIT(n)  asm volatile("cp.async.wait_group %0;" :: "n"(n) : "memory")

__device__ __forceinline__ unsigned packbf(__nv_bfloat16 a, __nv_bfloat16 b){
    return (unsigned)__bfloat16_as_ushort(a) | ((unsigned)__bfloat16_as_ushort(b) << 16);
}
// pack two fp32 -> bf16x2 (lo_f -> low half, hi_f -> high half), 1 instr
__device__ __forceinline__ unsigned cvt2bf(float hi_f, float lo_f){
    unsigned r; asm("cvt.rn.bf16x2.f32 %0, %1, %2;" : "=r"(r) : "f"(hi_f), "f"(lo_f)); return r;
}

// ================= K1: projections via split-bf16 HMMA =================
#define P_WH 0
#define P_WL 52224
#define P_XH 104448
#define P_XL 139264
#define P_SMEM 174080
__global__ void __launch_bounds__(256)
k_proj(const float* __restrict__ x, const float* __restrict__ w_qk,
       const float* __restrict__ w_v, const float* __restrict__ b_v,
       const float* __restrict__ w_x)
{
    extern __shared__ char smc[];
    unsigned sb = smem_u32(smc);
    int b = blockIdx.y, nt = blockIdx.x;
    int tid = threadIdx.x, wid = tid >> 5, lane = tid & 31;

    unsigned short* WH = (unsigned short*)(smc + P_WH);
    unsigned short* WL = (unsigned short*)(smc + P_WL);
    for (int i = tid; i < 24576; i += 256) {
        float wv = (i < 8192) ? w_qk[i] : (i < 16384 ? w_v[i - 8192] : w_x[i - 16384]);
        int row = i >> 7, cc = i & 127;
        __nv_bfloat16 h = __float2bfloat16(wv);
        __nv_bfloat16 l = __float2bfloat16(wv - __bfloat162float(h));
        WH[row * 136 + cc] = __bfloat16_as_ushort(h);
        WL[row * 136 + cc] = __bfloat16_as_ushort(l);
    }
    unsigned short* XH = (unsigned short*)(smc + P_XH);
    unsigned short* XL = (unsigned short*)(smc + P_XL);
    const float* xp = x + (size_t)(b * C_) * N_ + nt * 128;
    for (int i = tid; i < 16384; i += 256) {
        int c = i >> 7, n = i & 127;
        float v = xp[(size_t)c * N_ + n];
        __nv_bfloat16 h = __float2bfloat16(v);
        __nv_bfloat16 l = __float2bfloat16(v - __bfloat162float(h));
        XH[c * 136 + n] = __bfloat16_as_ushort(h);
        XL[c * 136 + n] = __bfloat16_as_ushort(l);
    }
    __syncthreads();

    int wn = wid >> 1, wm = wid & 1;
    int rm = wn * 48, cn = wm * 64;
    float c[3][8][4];
#pragma unroll
    for (int ti = 0; ti < 3; ti++)
#pragma unroll
        for (int tj = 0; tj < 8; tj++)
#pragma unroll
            for (int q = 0; q < 4; q++) c[ti][tj][q] = 0.f;

#pragma unroll
    for (int p = 0; p < 3; p++) {
        unsigned wa = sb + ((p == 2) ? P_WL : P_WH);
        unsigned xb = sb + ((p == 1) ? P_XL : P_XH);
#pragma unroll
        for (int ks = 0; ks < 8; ks++) {
            unsigned a[3][4];
#pragma unroll
            for (int ti = 0; ti < 3; ti++)
                ldsm_x4(a[ti], wa + (rm + ti * 16 + (lane & 15)) * 272 + ks * 32 + (lane >> 4) * 16);
#pragma unroll
            for (int tjp = 0; tjp < 4; tjp++) {
                unsigned bb[4];
                ldsm_x4_t(bb, xb + (ks * 16 + (lane & 15)) * 272
                              + (cn + tjp * 16 + ((lane >> 4) << 3)) * 2);
#pragma unroll
                for (int ti = 0; ti < 3; ti++) {
                    mma16816(c[ti][2 * tjp],     a[ti], bb);
                    mma16816(c[ti][2 * tjp + 1], a[ti], bb + 2);
                }
            }
        }
    }
    __syncthreads();

    unsigned short* qstage = (unsigned short*)(smc + P_XH);
#pragma unroll
    for (int ti = 0; ti < 3; ti++) {
        int r0 = rm + ti * 16;
        int r = r0 + (lane >> 2);
#pragma unroll
        for (int tj = 0; tj < 8; tj++) {
            int c0 = cn + tj * 8 + 2 * (lane & 3);
            float v0 = c[ti][tj][0], v1 = c[ti][tj][1], v2 = c[ti][tj][2], v3 = c[ti][tj][3];
            if (r0 < 64) {
                __nv_bfloat16 h0 = __float2bfloat16(v0), h1 = __float2bfloat16(v1);
                __nv_bfloat16 h2 = __float2bfloat16(v2), h3 = __float2bfloat16(v3);
                qstage[c0 * 128 + r]            = __bfloat16_as_ushort(h0);
                qstage[c0 * 128 + 64 + r]       = __bfloat16_as_ushort(__float2bfloat16(v0 - __bfloat162float(h0)));
                qstage[(c0 + 1) * 128 + r]      = __bfloat16_as_ushort(h1);
                qstage[(c0 + 1) * 128 + 64 + r] = __bfloat16_as_ushort(__float2bfloat16(v1 - __bfloat162float(h1)));
                qstage[c0 * 128 + r + 8]            = __bfloat16_as_ushort(h2);
                qstage[c0 * 128 + 64 + r + 8]       = __bfloat16_as_ushort(__float2bfloat16(v2 - __bfloat162float(h2)));
                qstage[(c0 + 1) * 128 + r + 8]      = __bfloat16_as_ushort(h3);
                qstage[(c0 + 1) * 128 + 64 + r + 8] = __bfloat16_as_ushort(__float2bfloat16(v3 - __bfloat162float(h3)));
            } else if (r0 < 128) {
                float ba = b_v[r - 64], bb2 = b_v[r - 56];
                *(float2*)&g_v[(size_t)(b * 64 + r - 64) * N_ + nt * 128 + c0] = make_float2(v0 + ba, v1 + ba);
                *(float2*)&g_v[(size_t)(b * 64 + r - 56) * N_ + nt * 128 + c0] = make_float2(v2 + bb2, v3 + bb2);
            } else {
                *(float2*)&g_xc[(size_t)(b * 64 + r - 128) * N_ + nt * 128 + c0] = make_float2(v0, v1);
                *(float2*)&g_xc[(size_t)(b * 64 + r - 120) * N_ + nt * 128 + c0] = make_float2(v2, v3);
            }
        }
    }
    __syncthreads();
    for (int i = tid; i < 2048; i += 256) {
        int row = i >> 4, cc = i & 15;
        ((uint4*)(g_qs + (size_t)(b * N_ + nt * 128 + row) * 128))[cc] =
            ((const uint4*)(qstage + row * 128))[cc];
    }
}

// ================= K2: symmetric E=Q^T Q, P=exp(E) upper tiles only, rowsums both sides ===
#define K2_AS 0
#define K2_BS 34816
#define K2_RED 0
#define K2_RDT 4096
#define K2_SMEM 69632
__global__ void __launch_bounds__(256, 2)
k_energy()
{
    extern __shared__ char smc[];
    unsigned sb = smem_u32(smc);
    int b = blockIdx.y;
    int tid = threadIdx.x, wid = tid >> 5, lane = tid & 31;

    int u = blockIdx.x, nt = 0;
    while (u >= 32 - nt) { u -= 32 - nt; nt++; }
    int mt = nt + u;

    {
        const uint4* asrc = (const uint4*)(g_qs + (size_t)(b * N_ + nt * 128) * 128);
        const uint4* bsrc = (const uint4*)(g_qs + (size_t)(b * N_ + mt * 128) * 128);
        for (int i = tid; i < 2048; i += 256) {
            int row = i >> 4, cc = i & 15;
            *(uint4*)(smc + K2_AS + row * 272 + cc * 16) = asrc[i];
            *(uint4*)(smc + K2_BS + row * 272 + cc * 16) = bsrc[i];
        }
    }
    __syncthreads();

    int wn = wid >> 1, wm = wid & 1;
    int rn = wn * 32, cm = wm * 64;
    float c[2][8][4];
#pragma unroll
    for (int ti = 0; ti < 2; ti++)
#pragma unroll
        for (int tj = 0; tj < 8; tj++)
#pragma unroll
            for (int q = 0; q < 4; q++) c[ti][tj][q] = 0.f;

    const int qa[3] = {0, 0, 1}, qb[3] = {0, 1, 0};
#pragma unroll
    for (int s = 0; s < 12; s++) {
        int grp = s >> 2, km = (s & 3) * 32;
        int ka = qa[grp] * 128 + km, kb = qb[grp] * 128 + km;
        unsigned a[2][4];
#pragma unroll
        for (int ti = 0; ti < 2; ti++)
            ldsm_x4(a[ti], sb + K2_AS + (rn + ti * 16 + (lane & 15)) * 272 + ka + (lane >> 4) * 16);
#pragma unroll
        for (int tjp = 0; tjp < 4; tjp++) {
            unsigned bb[4];
            ldsm_x4(bb, sb + K2_BS + (cm + tjp * 16 + ((lane >> 4) << 3) + (lane & 7)) * 272
                        + kb + ((lane >> 3) & 1) * 16);
            mma16816(c[0][2*tjp],   a[0], bb);     mma16816(c[1][2*tjp],   a[1], bb);
            mma16816(c[0][2*tjp+1], a[0], bb + 2); mma16816(c[1][2*tjp+1], a[1], bb + 2);
        }
    }

    bool offd = (mt != nt);
    float rsA[2] = {0.f, 0.f}, rsB[2] = {0.f, 0.f};
    float colp0[8], colp1[8];
#pragma unroll
    for (int tj = 0; tj < 8; tj++) { colp0[tj] = 0.f; colp1[tj] = 0.f; }
    size_t prow = (size_t)(b * N_ + nt * 128) * N_ + mt * 128;
#pragma unroll
    for (int ti = 0; ti < 2; ti++) {
        int r0 = rn + ti * 16 + (lane >> 2);
#pragma unroll
        for (int tj = 0; tj < 8; tj++) {
            int c0 = cm + tj * 8 + 2 * (lane & 3);
            float p0 = __expf(c[ti][tj][0]), p1 = __expf(c[ti][tj][1]);
            float p2 = __expf(c[ti][tj][2]), p3 = __expf(c[ti][tj][3]);
            rsA[ti] += p0 + p1;  rsB[ti] += p2 + p3;
            colp0[tj] += p0 + p2; colp1[tj] += p1 + p3;
            // truncation split: h = top16(p) via PRMT, l = p - masked(p) via cvt.bf16x2
            unsigned u0 = __float_as_uint(p0), u1 = __float_as_uint(p1);
            unsigned u2 = __float_as_uint(p2), u3 = __float_as_uint(p3);
            float l0 = p0 - __uint_as_float(u0 & 0xFFFF0000u);
            float l1 = p1 - __uint_as_float(u1 & 0xFFFF0000u);
            float l2 = p2 - __uint_as_float(u2 & 0xFFFF0000u);
            float l3 = p3 - __uint_as_float(u3 & 0xFFFF0000u);
            size_t ba = prow + (size_t)r0 * N_ + c0;
            size_t bc = ba + (size_t)8 * N_;
            *(unsigned*)(g_ph + ba) = __byte_perm(u0, u1, 0x7632);
            *(unsigned*)(g_ph + bc) = __byte_perm(u2, u3, 0x7632);
            *(unsigned*)(g_pl + ba) = cvt2bf(l1, l0);
            *(unsigned*)(g_pl + bc) = cvt2bf(l3, l2);
        }
    }
    if (offd) {
#pragma unroll
        for (int tj = 0; tj < 8; tj++) {
            colp0[tj] += __shfl_xor_sync(0xffffffff, colp0[tj], 4);
            colp0[tj] += __shfl_xor_sync(0xffffffff, colp0[tj], 8);
            colp0[tj] += __shfl_xor_sync(0xffffffff, colp0[tj], 16);
            colp1[tj] += __shfl_xor_sync(0xffffffff, colp1[tj], 4);
            colp1[tj] += __shfl_xor_sync(0xffffffff, colp1[tj], 8);
            colp1[tj] += __shfl_xor_sync(0xffffffff, colp1[tj], 16);
        }
    }
    __syncthreads();

    float* red  = (float*)(smc + K2_RED);
    float* redT = (float*)(smc + K2_RDT);
#pragma unroll
    for (int ti = 0; ti < 2; ti++) {
        int r0 = rn + ti * 16 + (lane >> 2);
        red[r0 * 8 + wm * 4 + (lane & 3)]       = rsA[ti];
        red[(r0 + 8) * 8 + wm * 4 + (lane & 3)] = rsB[ti];
    }
    if (offd && lane < 4) {
#pragma unroll
        for (int tj = 0; tj < 8; tj++) {
            redT[wn * 128 + cm + tj * 8 + 2 * lane]     = colp0[tj];
            redT[wn * 128 + cm + tj * 8 + 2 * lane + 1] = colp1[tj];
        }
    }
    __syncthreads();
    if (tid < 128) {
        float s = 0.f;
#pragma unroll
        for (int j = 0; j < 8; j++) s += red[tid * 8 + j];
        g_rspart[((size_t)(b * 32 + nt) * 32 + mt) * 128 + tid] = s;
        if (offd) {
            float st = redT[tid] + redT[128 + tid] + redT[256 + tid] + redT[384 + tid];
            g_rspart[((size_t)(b * 32 + mt) * 32 + nt) * 128 + tid] = st;
        }
    }
}

// ================= K2.5: rowsum reduce -> invsbf, Av = v*inv split (merged) =================
__global__ void k_rowav()
{
    int idx = blockIdx.x * 256 + threadIdx.x;
    int b = idx >> 12, n = idx & 4095;
    float s = 0.f;
    const float* p = g_rspart + ((size_t)(b * 32 + (n >> 7)) * 32) * 128 + (n & 127);
#pragma unroll
    for (int mt = 0; mt < 32; mt++) s += p[mt * 128];
    float inv = 1.0f / s;
    __nv_bfloat16 ih = __float2bfloat16(inv);
    g_invsbf[(b * 2 + 0) * N_ + n] = ih;
    g_invsbf[(b * 2 + 1) * N_ + n] = __float2bfloat16(inv - __bfloat162float(ih));
    const float* vs = g_v + (size_t)(b * 64) * N_ + n;
    __nv_bfloat16* avh = g_av + (size_t)(b * 128) * N_ + n;
#pragma unroll 4
    for (int o = 0; o < 64; o++) {
        float a = vs[(size_t)o * N_] * inv;
        __nv_bfloat16 h = __float2bfloat16(a);
        avh[(size_t)o * N_]        = h;
        avh[(size_t)(o + 64) * N_] = __float2bfloat16(a - __bfloat162float(h));
    }
}

// ================= K3: D = Ah@(Ph+Pl) + Al@Ph; 512 thr, 16 warp-tiles, 3-stage cp.async ===
// grid (16, 8); each block: 2 mt tiles of 128 cols. Warp: 16 hi-rows + 16 lo-rows x 32 cols.
#define K3T      512
#define K3_WT    0           // 16384
#define K3_CS2   16384       // [4][128] f32
#define K3_CS    18432       // [128] f32
#define K3_STG   21504
#define K3_SSZ   57600       // A 18432 | H 18432 | L 18432 | INV 2304
#define K3_RED   (K3_STG + 69632)    // after Ds(67584): [64][8]x2 f32 = 4096
#define K3_SMEM  (21504 + 3*57600)
__device__ __forceinline__ void k3_issue(unsigned sb, int st, int b, int mta, int ch, int tid)
{
    unsigned s0 = sb + K3_STG + st * K3_SSZ;
    int nb = ch << 6;
    bool tr = (mta > (ch >> 1));
    const __nv_bfloat16* asrc = g_av + (size_t)b * 128 * N_ + nb;
    const __nv_bfloat16 *hsrc, *lsrc;
    if (!tr) {
        hsrc = g_ph + ((size_t)(b * N_ + mta * 128)) * N_ + nb;
        lsrc = g_pl + ((size_t)(b * N_ + mta * 128)) * N_ + nb;
    } else {
        hsrc = g_ph + ((size_t)(b * N_ + nb)) * N_ + mta * 128;
        lsrc = g_pl + ((size_t)(b * N_ + nb)) * N_ + mta * 128;
    }
    for (int i = tid; i < 1024; i += K3T) {
        int ar = i >> 3, ac = i & 7;
        cp16(s0 + ar * 144 + ac * 16, asrc + (size_t)ar * N_ + ac * 8);
        if (!tr) {
            cp16(s0 + 18432 + ar * 144 + ac * 16, hsrc + (size_t)ar * N_ + ac * 8);
            cp16(s0 + 36864 + ar * 144 + ac * 16, lsrc + (size_t)ar * N_ + ac * 8);
        } else {
            int rr = i >> 4, cc = i & 15;
            cp16(s0 + 18432 + rr * 272 + cc * 16, hsrc + (size_t)rr * N_ + cc * 8);
            cp16(s0 + 36864 + rr * 272 + cc * 16, lsrc + (size_t)rr * N_ + cc * 8);
        }
    }
    if (tid < 16) {
        int row = tid >> 3, cc = tid & 7;
        cp16(s0 + 55296 + row * 144 + cc * 16,
             g_invsbf + (size_t)(b * 2 + row) * N_ + nb + cc * 8);
    }
}

__global__ void __launch_bounds__(K3T)
k_attn(const float* __restrict__ w_t, const float* __restrict__ b_t)
{
    extern __shared__ char smc[];
    unsigned sb = smem_u32(smc);
    int b = blockIdx.y;
    int tid = threadIdx.x, wid = tid >> 5, lane = tid & 31;
    float* Wts = (float*)(smc + K3_WT);
    float* cs2 = (float*)(smc + K3_CS2);
    float* cs  = (float*)(smc + K3_CS);

    for (int i = tid; i < 4096; i += K3T) Wts[i] = w_t[i];
    for (int st = 0; st < 3; st++)
        for (int i = tid; i < 504; i += K3T)
            *(unsigned*)(smc + K3_STG + st * K3_SSZ + 55296 + 288 + i * 4) = 0;

    int wn = wid >> 2, wm = wid & 3;        // 16 warps: 4 row groups x 4 col groups
    int rh = wn * 16, rl = 64 + wn * 16;    // each warp: 16 hi-rows + 16 lo-rows
    int cm = wm * 32;

#pragma unroll 1
    for (int half = 0; half < 2; half++) {
        int mta = blockIdx.x * 2 + half;
        float c[2][4][4], ccs[4][4];
#pragma unroll
        for (int tj = 0; tj < 4; tj++) {
#pragma unroll
            for (int q = 0; q < 4; q++) { c[0][tj][q] = 0.f; c[1][tj][q] = 0.f; ccs[tj][q] = 0.f; }
        }
        __syncthreads();
        k3_issue(sb, 0, b, mta, 0, tid); CP_COMMIT();
        k3_issue(sb, 1, b, mta, 1, tid); CP_COMMIT();

        for (int ch = 0; ch < 64; ch++) {
            if (ch + 2 < 64) CP_WAIT(1); else CP_WAIT(0);
            __syncthreads();
            if (ch + 2 < 64) { k3_issue(sb, (ch + 2) % 3, b, mta, ch + 2, tid); CP_COMMIT(); }

            unsigned sA = sb + K3_STG + (ch % 3) * K3_SSZ;
            unsigned sH = sA + 18432, sL = sA + 36864, sI = sA + 55296;
            bool tr = (mta > (ch >> 1));
            if (!tr) {
#pragma unroll
                for (int ks = 0; ks < 4; ks++) {
                    unsigned a0[4], a1[4], ainv[4];
                    ldsm_x4(a0, sA + (rh + (lane & 15)) * 144 + ks * 32 + (lane >> 4) * 16);
                    ldsm_x4(a1, sA + (rl + (lane & 15)) * 144 + ks * 32 + (lane >> 4) * 16);
                    bool mine = (ks == wn);
                    if (mine) ldsm_x4(ainv, sI + (lane & 15) * 144 + ks * 32 + (lane >> 4) * 16);
                    unsigned pbase = (lane >> 4) ? sL : sH;
#pragma unroll
                    for (int tjp = 0; tjp < 2; tjp++) {
                        int t0 = 2 * tjp, t1 = t0 + 1;
                        unsigned b0[4], b1[4];
                        ldsm_x4(b0, pbase + (cm + t0 * 8 + (lane & 7)) * 144 + ks * 32 + ((lane >> 3) & 1) * 16);
                        ldsm_x4(b1, pbase + (cm + t1 * 8 + (lane & 7)) * 144 + ks * 32 + ((lane >> 3) & 1) * 16);
                        mma16816(c[0][t0], a0, b0);     mma16816(c[1][t0], a1, b0);
                        mma16816(c[0][t1], a0, b1);     mma16816(c[1][t1], a1, b1);
                        mma16816(c[0][t0], a0, b0 + 2); mma16816(c[0][t1], a0, b1 + 2);  // Al@Pl dropped
                        if (mine) {
                            mma16816(ccs[t0], ainv, b0);     mma16816(ccs[t1], ainv, b1);
                            mma16816(ccs[t0], ainv, b0 + 2); mma16816(ccs[t1], ainv, b1 + 2);
                        }
                    }
                }
            } else {
#pragma unroll
                for (int ks = 0; ks < 4; ks++) {
                    unsigned a0[4], a1[4], ainv[4];
                    ldsm_x4(a0, sA + (rh + (lane & 15)) * 144 + ks * 32 + (lane >> 4) * 16);
                    ldsm_x4(a1, sA + (rl + (lane & 15)) * 144 + ks * 32 + (lane >> 4) * 16);
                    bool mine = (ks == wn);
                    if (mine) ldsm_x4(ainv, sI + (lane & 15) * 144 + ks * 32 + (lane >> 4) * 16);
                    unsigned pbase = (lane >> 4) ? sL : sH;
                    unsigned krow = (ks * 16 + (lane & 15)) * 272;
#pragma unroll
                    for (int tjp = 0; tjp < 2; tjp++) {
                        int t0 = 2 * tjp, t1 = t0 + 1;
                        unsigned b0[4], b1[4];
                        ldsm_x4_t(b0, pbase + krow + (cm + t0 * 8) * 2);
                        ldsm_x4_t(b1, pbase + krow + (cm + t1 * 8) * 2);
                        mma16816(c[0][t0], a0, b0);     mma16816(c[1][t0], a1, b0);
                        mma16816(c[0][t1], a0, b1);     mma16816(c[1][t1], a1, b1);
                        mma16816(c[0][t0], a0, b0 + 2); mma16816(c[0][t1], a0, b1 + 2);  // Al@Pl dropped
                        if (mine) {
                            mma16816(ccs[t0], ainv, b0);     mma16816(ccs[t1], ainv, b1);
                            mma16816(ccs[t0], ainv, b0 + 2); mma16816(ccs[t1], ainv, b1 + 2);
                        }
                    }
                }
            }
        }
#pragma unroll
        for (int tj = 0; tj < 4; tj++) {
            float v0 = ccs[tj][0] + __shfl_xor_sync(0xffffffff, ccs[tj][0], 4);
            float v1 = ccs[tj][1] + __shfl_xor_sync(0xffffffff, ccs[tj][1], 4);
            if (lane < 4) {
                cs2[wn * 128 + cm + tj * 8 + 2 * lane]     = v0;
                cs2[wn * 128 + cm + tj * 8 + 2 * lane + 1] = v1;
            }
        }
        __syncthreads();
        if (tid < 128)
            cs[tid] = cs2[tid] + cs2[128 + tid] + cs2[256 + tid] + cs2[384 + tid];
        __syncthreads();

        float* Ds = (float*)(smc + K3_STG);
#pragma unroll
        for (int ti = 0; ti < 2; ti++) {
            int r0 = (ti == 0 ? rh : rl) + (lane >> 2);
#pragma unroll
            for (int tj = 0; tj < 4; tj++) {
                int c0 = cm + tj * 8 + 2 * (lane & 3);
                *(float2*)&Ds[r0 * 132 + c0]       = make_float2(c[ti][tj][0], c[ti][tj][1]);
                *(float2*)&Ds[(r0 + 8) * 132 + c0] = make_float2(c[ti][tj][2], c[ti][tj][3]);
            }
        }
        __syncthreads();

        int o = tid >> 3, g = tid & 7;      // 64 channels x 8 col-groups of 16
        {
            const float* xcb = g_xc + (size_t)(b * 64 + o) * N_ + mta * 128;
#pragma unroll 4
            for (int k = 0; k < 16; k++) {
                int m = g * 16 + k;
                float xru = Ds[o * 132 + m] + Ds[(o + 64) * 132 + m];
                Ds[o * 132 + m] = xcb[m] - xru / (1e-9f + cs[m]);
            }
        }
        __syncthreads();

        {
            float bias = b_t[o];
            float psum = 0.f, psq = 0.f;
            float* tout = g_t + (size_t)(b * 64 + o) * N_ + mta * 128;
            int m0 = g * 16;
            float acc[16];
#pragma unroll
            for (int j = 0; j < 16; j++) acc[j] = 0.f;
#pragma unroll 4
            for (int k = 0; k < 64; k++) {
                float w = Wts[o * 64 + k];
                const float4* dr = (const float4*)&Ds[k * 132 + m0];
#pragma unroll
                for (int q = 0; q < 4; q++) {
                    float4 d4 = dr[q];
                    acc[4*q]   += w * d4.x; acc[4*q+1] += w * d4.y;
                    acc[4*q+2] += w * d4.z; acc[4*q+3] += w * d4.w;
                }
            }
#pragma unroll
            for (int j = 0; j < 16; j += 4) {
                float t0 = acc[j] + bias, t1 = acc[j+1] + bias, t2 = acc[j+2] + bias, t3 = acc[j+3] + bias;
                *(float4*)&tout[m0 + j] = make_float4(t0, t1, t2, t3);
                psum += t0 + t1 + t2 + t3;
                psq  += t0*t0 + t1*t1 + t2*t2 + t3*t3;
            }
            float* Rs = (float*)(smc + K3_RED);
            float* Rq = Rs + 512;
            Rs[o * 8 + g] = psum;
            Rq[o * 8 + g] = psq;
            __syncthreads();
            if (tid < 64) {
                float s = 0.f, q = 0.f;
#pragma unroll
                for (int j = 0; j < 8; j++) { s += Rs[tid * 8 + j]; q += Rq[tid * 8 + j]; }
                int blk = b * 32 + mta;
                g_part[tid * 256 + blk]            = s;
                g_part[64 * 256 + tid * 256 + blk] = q;
            }
        }
    }
}

// ================= K5: BN stats =================
__global__ void k_bnstats(const float* __restrict__ gamma, const float* __restrict__ beta)
{
    int c = threadIdx.x;
    if (c >= 64) return;
    float s = 0.f, q = 0.f;
    for (int j = 0; j < 256; j++) {
        s += g_part[c * 256 + j];
        q += g_part[64 * 256 + c * 256 + j];
    }
    const float invN = 1.0f / 32768.0f;
    float mean = s * invN;
    float var  = q * invN - mean * mean;
    float sc = gamma[c] * rsqrtf(var + 1e-5f);
    g_bn[c]      = sc;
    g_bn[64 + c] = beta[c] - mean * sc;
}

// ================= K6: out = x_c + relu(scale*t + shift) =================
__global__ void k_final(float* __restrict__ out)
{
    int i4 = blockIdx.x * 256 + threadIdx.x;
    if (i4 >= B_ * C2_ * (N_ / 4)) return;
    int ch = (i4 >> 10) & 63;
    float sc = g_bn[ch], sh = g_bn[64 + ch];
    float4 t  = ((const float4*)g_t)[i4];
    float4 xc = ((const float4*)g_xc)[i4];
    float4 r;
    r.x = xc.x + fmaxf(0.f, sc * t.x + sh);
    r.y = xc.y + fmaxf(0.f, sc * t.y + sh);
    r.z = xc.z + fmaxf(0.f, sc * t.z + sh);
    r.w = xc.w + fmaxf(0.f, sc * t.w + sh);
    ((float4*)out)[i4] = r;
}

// ================= launch =================
extern "C" void kernel_launch(void* const* d_in, const int* in_sizes, int n_in,
                              void* d_out, int out_size)
{
    const float* x     = (const float*)d_in[0];
    const float* w_qk  = (const float*)d_in[1];
    const float* w_v   = (const float*)d_in[2];
    const float* b_v   = (const float*)d_in[3];
    const float* w_x   = (const float*)d_in[4];
    const float* w_t   = (const float*)d_in[5];
    const float* b_t   = (const float*)d_in[6];
    const float* gamma = (const float*)d_in[7];
    const float* beta  = (const float*)d_in[8];
    float* out = (float*)d_out;

    cudaFuncSetAttribute(k_proj,   cudaFuncAttributeMaxDynamicSharedMemorySize, P_SMEM);
    cudaFuncSetAttribute(k_energy, cudaFuncAttributeMaxDynamicSharedMemorySize, K2_SMEM);
    cudaFuncSetAttribute(k_attn,   cudaFuncAttributeMaxDynamicSharedMemorySize, K3_SMEM);

    k_proj    <<<dim3(32, 8), 256, P_SMEM>>>(x, w_qk, w_v, b_v, w_x);
    k_energy  <<<dim3(528, 8), 256, K2_SMEM>>>();
    k_rowav   <<<128, 256>>>();
    k_attn    <<<dim3(16, 8), K3T, K3_SMEM>>>(w_t, b_t);
    k_bnstats <<<1, 64>>>(gamma, beta);
    k_final   <<<2048, 256>>>(out);
}